// round 14
// baseline (speedup 1.0000x reference)
#include <cuda_runtime.h>
#include <cuda_bf16.h>
#include <math.h>
#include <cstdint>

// Problem constants
#define BB 16
#define NN 1024
#define DD 256
#define HH 8
#define INF_ 256
#define HID 1024
#define MROWS (BB * NN)   // 16384

// -------- scratch (device globals; no allocation allowed) --------
__device__ float g_h   [MROWS * DD];
__device__ float g_qkv [MROWS * 3 * INF_];
__device__ float g_o   [MROWS * INF_];
__device__ float g_xn  [MROWS * DD];
__device__ float g_h2  [MROWS * DD];
__device__ float g_mid [MROWS * HID];

// ===================== helpers =====================
__device__ __forceinline__ uint32_t smem_u32(const void* p) {
    uint32_t a;
    asm("{ .reg .u64 t; cvta.to.shared.u64 t, %1; cvt.u32.u64 %0, t; }"
        : "=r"(a) : "l"(p));
    return a;
}

#define CP_ASYNC16(dst, src) \
    asm volatile("cp.async.cg.shared.global [%0], [%1], 16;" :: "r"(dst), "l"(src))
#define CP_COMMIT() asm volatile("cp.async.commit_group;" ::: "memory")
#define CP_WAIT(n)  asm volatile("cp.async.wait_group %0;" :: "n"(n) : "memory")

// m16n8k8 tf32 mma (portable at plain sm_103 target)
#define MMA_TF32(c, a, b) \
    asm volatile("mma.sync.aligned.m16n8k8.row.col.f32.tf32.tf32.f32 " \
        "{%0,%1,%2,%3}, {%4,%5,%6,%7}, {%8,%9}, {%0,%1,%2,%3};" \
        : "+f"((c)[0]), "+f"((c)[1]), "+f"((c)[2]), "+f"((c)[3]) \
        : "r"((a)[0]), "r"((a)[1]), "r"((a)[2]), "r"((a)[3]), \
          "r"((b)[0]), "r"((b)[1]))

// ======================= LayerNorm ==============================
__global__ __launch_bounds__(256) void ln_kernel(
    const float* __restrict__ x, const float* __restrict__ g,
    const float* __restrict__ b, float* __restrict__ out)
{
    int row = blockIdx.x;
    int t = threadIdx.x;
    float v = x[row * DD + t];
    float s1 = v, s2 = v * v;
    #pragma unroll
    for (int o = 16; o; o >>= 1) {
        s1 += __shfl_xor_sync(0xffffffffu, s1, o);
        s2 += __shfl_xor_sync(0xffffffffu, s2, o);
    }
    __shared__ float r1[8], r2[8];
    if ((t & 31) == 0) { r1[t >> 5] = s1; r2[t >> 5] = s2; }
    __syncthreads();
    float S1 = 0.f, S2 = 0.f;
    #pragma unroll
    for (int i = 0; i < 8; i++) { S1 += r1[i]; S2 += r2[i]; }
    float mu  = S1 * (1.0f / DD);
    float var = S2 * (1.0f / DD) - mu * mu;
    float inv = rsqrtf(var + 1e-5f);
    out[row * DD + t] = (v - mu) * inv * g[t] + b[t];
}

// ============ tf32 mma.sync GEMM: C[M,N] = A[M,K]@B[N,K]^T + epilogue =======
// Tile 64x128, 8 warps (2x4), warp tile 32x32, BK=32, 2-stage cp.async,
// ks-level fragment double buffering. ~80 regs + 55KB smem -> 3 CTAs/SM
// (6 warps/SMSP) and 2x the CTA count for machine fill.
#define PAD 36
#define ASZ (64 * PAD)            // A stage floats
#define BSZ (128 * PAD)           // B stage floats
#define STG (ASZ + BSZ)           // one stage
#define GEMM_DYN_BYTES (2 * STG * 4)   // 55296 B

template <bool GELU>
__global__ __launch_bounds__(256, 3) void gemm_mma(
    const float* __restrict__ A, const float* __restrict__ Bm,
    const float* __restrict__ bias,
    const float* __restrict__ res1, const float* __restrict__ res2,
    float* __restrict__ C, int M, int Nn, int K)
{
    extern __shared__ float sm[];

    const int tid = threadIdx.x;
    const int wid = tid >> 5, lane = tid & 31;
    const int bm = blockIdx.y * 64;
    const int bn = blockIdx.x * 128;
    const int wm = (wid >> 2) * 32;   // 0 / 32
    const int wn = (wid & 3) * 32;    // 0..96

    // A loader: 64 rows x 32 floats = 512 float4; 2 per thread
    const int ar  = tid >> 2;          // 0..63
    const int acb = (tid & 3) * 8;     // 0,8,16,24
    // B loader: 128 rows x 32 floats = 1024 float4; 4 per thread
    const int br  = tid >> 1;          // 0..127
    const int bcb = (tid & 1) * 16;    // 0,16

    const float* Ag = A  + (size_t)(bm + ar) * K + acb;
    const float* Bg = Bm + (size_t)(bn + br) * K + bcb;
    const uint32_t sBase = smem_u32(sm);
    const uint32_t stageBytes = STG * 4;
    const uint32_t sAoff = (ar * PAD + acb) * 4;
    const uint32_t sBoff = (ASZ + br * PAD + bcb) * 4;

    float acc[2][4][4];
    #pragma unroll
    for (int mt = 0; mt < 2; mt++)
        #pragma unroll
        for (int nt = 0; nt < 4; nt++)
            #pragma unroll
            for (int q = 0; q < 4; q++) acc[mt][nt][q] = 0.f;

    const int NC = K >> 5;

    // prologue: chunk 0 -> stage 0
    {
        CP_ASYNC16(sBase + sAoff,      Ag);
        CP_ASYNC16(sBase + sAoff + 16, Ag + 4);
        #pragma unroll
        for (int i = 0; i < 4; i++)
            CP_ASYNC16(sBase + sBoff + i * 16, Bg + i * 4);
        CP_COMMIT();
    }

    const int gr = lane >> 2;
    const int tc = lane & 3;

    for (int cc = 0; cc < NC; cc++) {
        if (cc + 1 < NC) {
            const uint32_t sb = sBase + ((cc + 1) & 1) * stageBytes;
            const float* ap = Ag + (cc + 1) * 32;
            const float* bp = Bg + (cc + 1) * 32;
            CP_ASYNC16(sb + sAoff,      ap);
            CP_ASYNC16(sb + sAoff + 16, ap + 4);
            #pragma unroll
            for (int i = 0; i < 4; i++)
                CP_ASYNC16(sb + sBoff + i * 16, bp + i * 4);
            CP_COMMIT();
            CP_WAIT(1);
        } else {
            CP_WAIT(0);
        }
        __syncthreads();

        const float* sA = sm + (cc & 1) * STG;
        const float* sB = sA + ASZ;

        uint32_t bfrag[2][4][2];
        uint32_t afrag[2][2][4];

        #pragma unroll
        for (int nt = 0; nt < 4; nt++) {
            const int n0 = wn + nt * 8 + gr;
            bfrag[0][nt][0] = __float_as_uint(sB[n0 * PAD + tc]);
            bfrag[0][nt][1] = __float_as_uint(sB[n0 * PAD + tc + 4]);
        }
        #pragma unroll
        for (int mt = 0; mt < 2; mt++) {
            const int r = wm + mt * 16 + gr;
            afrag[0][mt][0] = __float_as_uint(sA[r * PAD + tc]);
            afrag[0][mt][1] = __float_as_uint(sA[(r + 8) * PAD + tc]);
            afrag[0][mt][2] = __float_as_uint(sA[r * PAD + tc + 4]);
            afrag[0][mt][3] = __float_as_uint(sA[(r + 8) * PAD + tc + 4]);
        }

        #pragma unroll
        for (int ks = 0; ks < 4; ks++) {
            const int cur = ks & 1, nxt = cur ^ 1;
            if (ks < 3) {
                const int kb = (ks + 1) * 8;
                #pragma unroll
                for (int nt = 0; nt < 4; nt++) {
                    const int n0 = wn + nt * 8 + gr;
                    bfrag[nxt][nt][0] = __float_as_uint(sB[n0 * PAD + kb + tc]);
                    bfrag[nxt][nt][1] = __float_as_uint(sB[n0 * PAD + kb + tc + 4]);
                }
                #pragma unroll
                for (int mt = 0; mt < 2; mt++) {
                    const int r = wm + mt * 16 + gr;
                    afrag[nxt][mt][0] = __float_as_uint(sA[r * PAD + kb + tc]);
                    afrag[nxt][mt][1] = __float_as_uint(sA[(r + 8) * PAD + kb + tc]);
                    afrag[nxt][mt][2] = __float_as_uint(sA[r * PAD + kb + tc + 4]);
                    afrag[nxt][mt][3] = __float_as_uint(sA[(r + 8) * PAD + kb + tc + 4]);
                }
            }
            #pragma unroll
            for (int mt = 0; mt < 2; mt++)
                #pragma unroll
                for (int nt = 0; nt < 4; nt++)
                    MMA_TF32(acc[mt][nt], afrag[cur][mt], bfrag[cur][nt]);
        }
        __syncthreads();
    }

    #pragma unroll
    for (int mt = 0; mt < 2; mt++) {
        #pragma unroll
        for (int nt = 0; nt < 4; nt++) {
            const int col = bn + wn + nt * 8 + 2 * tc;
            #pragma unroll
            for (int half = 0; half < 2; half++) {
                const int row = bm + wm + mt * 16 + gr + half * 8;
                float v0 = acc[mt][nt][half * 2 + 0];
                float v1 = acc[mt][nt][half * 2 + 1];
                if (bias) { v0 += bias[col]; v1 += bias[col + 1]; }
                if (GELU) {
                    v0 = 0.5f * v0 * (1.0f + erff(v0 * 0.70710678118654752f));
                    v1 = 0.5f * v1 * (1.0f + erff(v1 * 0.70710678118654752f));
                }
                const size_t idx = (size_t)row * Nn + col;
                if (res1) { v0 += res1[idx]; v1 += res1[idx + 1]; }
                if (res2) { v0 += res2[idx]; v1 += res2[idx + 1]; }
                *(float2*)(C + idx) = make_float2(v0, v1);
            }
        }
    }
}

// ====== Attention: tensor-core flash, plain tf32 QK and PV ==================
// CTA: 128 q-rows of one (b,h); 8 warps, warp w owns q rows [w*16, w*16+16).
// 8 K-tiles of 128 keys. Q,K pad-36; Vt[32][132]; P pad-132.
#define PADJ 132
#define PADP 132
#define AQ_OFF 0                        // Qs [128][36]
#define AK_OFF (128 * PAD)              // Ks [128][36]
#define AV_OFF (AK_OFF + 128 * PAD)     // Vt [32][132]
#define AP_OFF (AV_OFF + 32 * PADJ)     // Ps [128][132]
#define ATTN_SMEM_FLOATS (AP_OFF + 128 * PADP)
#define ATTN_DYN_BYTES   (ATTN_SMEM_FLOATS * 4)

__global__ __launch_bounds__(256) void attn_kernel(
    const float* __restrict__ qkv, float* __restrict__ o)
{
    extern __shared__ float sm[];
    float* Qs = sm + AQ_OFF;
    float* Ks = sm + AK_OFF;
    float* Vt = sm + AV_OFF;
    float* Ps = sm + AP_OFF;

    const int tid = threadIdx.x;
    const int b = blockIdx.y >> 3, h = blockIdx.y & 7;
    const int q0 = blockIdx.x * 128;
    const int w = tid >> 5, lane = tid & 31;
    const int gr = lane >> 2, tc = lane & 3;
    const int qm = w * 16;
    const int par = tid & 1;
    const float scale = 0.17677669529663687f; // 1/sqrt(32)

    // ---- load Q tile (scaled) ----
    {
        const int rr = tid >> 1, cb = par * 16;
        const float* qp = qkv + ((size_t)(b * NN + q0 + rr) * 768) + h * 32 + cb;
        #pragma unroll
        for (int i = 0; i < 16; i += 4) {
            float4 v = *(const float4*)(qp + i);
            Qs[rr * PAD + cb + i + 0] = v.x * scale;
            Qs[rr * PAD + cb + i + 1] = v.y * scale;
            Qs[rr * PAD + cb + i + 2] = v.z * scale;
            Qs[rr * PAD + cb + i + 3] = v.w * scale;
        }
    }

    float oa[4][4];
    #pragma unroll
    for (int nf = 0; nf < 4; nf++)
        #pragma unroll
        for (int q = 0; q < 4; q++) oa[nf][q] = 0.f;
    float m0 = -1e30f, m1 = -1e30f, l0 = 0.f, l1 = 0.f;

    for (int kt = 0; kt < NN / 128; kt++) {   // 8 tiles — exactly N=1024 keys
        const int k0 = kt * 128;
        __syncthreads();   // protect Ks/Vt from previous tile's readers
        // ---- load K (rows) and V (transposed) ----
        {
            const int rr = tid >> 1, cb = par * 16;
            const float* kp = qkv + ((size_t)(b * NN + k0 + rr) * 768) + 256 + h * 32 + cb;
            const float* vp = kp + 256;
            float vv[16];
            #pragma unroll
            for (int i = 0; i < 16; i += 4) {
                float4 kv = *(const float4*)(kp + i);
                Ks[rr * PAD + cb + i + 0] = kv.x;
                Ks[rr * PAD + cb + i + 1] = kv.y;
                Ks[rr * PAD + cb + i + 2] = kv.z;
                Ks[rr * PAD + cb + i + 3] = kv.w;
                float4 vq = *(const float4*)(vp + i);
                vv[i + 0] = vq.x; vv[i + 1] = vq.y; vv[i + 2] = vq.z; vv[i + 3] = vq.w;
            }
            #pragma unroll
            for (int ii = 0; ii < 16; ii++) {     // parity stagger kills 2-way conflict
                int i = (ii + par) & 15;
                Vt[(cb + i) * PADJ + rr] = vv[i];
            }
        }
        __syncthreads();

        // ---- QK^T: plain tf32 ----
        float sc[16][4];
        #pragma unroll
        for (int nf = 0; nf < 16; nf++)
            #pragma unroll
            for (int q = 0; q < 4; q++) sc[nf][q] = 0.f;
        #pragma unroll
        for (int ks = 0; ks < 4; ks++) {
            const int kb = ks * 8;
            uint32_t afrag[4];
            afrag[0] = __float_as_uint(Qs[(qm + gr) * PAD + kb + tc]);
            afrag[1] = __float_as_uint(Qs[(qm + gr + 8) * PAD + kb + tc]);
            afrag[2] = __float_as_uint(Qs[(qm + gr) * PAD + kb + tc + 4]);
            afrag[3] = __float_as_uint(Qs[(qm + gr + 8) * PAD + kb + tc + 4]);
            #pragma unroll
            for (int nf = 0; nf < 16; nf++) {
                uint32_t bfrag[2];
                bfrag[0] = __float_as_uint(Ks[(nf * 8 + gr) * PAD + kb + tc]);
                bfrag[1] = __float_as_uint(Ks[(nf * 8 + gr) * PAD + kb + tc + 4]);
                MMA_TF32(sc[nf], afrag, bfrag);
            }
        }

        // ---- online softmax on accumulator layout ----
        float tm0 = -1e30f, tm1 = -1e30f;
        #pragma unroll
        for (int nf = 0; nf < 16; nf++) {
            tm0 = fmaxf(tm0, fmaxf(sc[nf][0], sc[nf][1]));
            tm1 = fmaxf(tm1, fmaxf(sc[nf][2], sc[nf][3]));
        }
        tm0 = fmaxf(tm0, __shfl_xor_sync(0xffffffffu, tm0, 1));
        tm0 = fmaxf(tm0, __shfl_xor_sync(0xffffffffu, tm0, 2));
        tm1 = fmaxf(tm1, __shfl_xor_sync(0xffffffffu, tm1, 1));
        tm1 = fmaxf(tm1, __shfl_xor_sync(0xffffffffu, tm1, 2));
        float mn0 = fmaxf(m0, tm0), mn1 = fmaxf(m1, tm1);
        float corr0 = __expf(m0 - mn0), corr1 = __expf(m1 - mn1);
        m0 = mn0; m1 = mn1;
        float ls0 = 0.f, ls1 = 0.f;
        #pragma unroll
        for (int nf = 0; nf < 16; nf++) {
            float p0 = __expf(sc[nf][0] - mn0);
            float p1 = __expf(sc[nf][1] - mn0);
            float p2 = __expf(sc[nf][2] - mn1);
            float p3 = __expf(sc[nf][3] - mn1);
            ls0 += p0 + p1; ls1 += p2 + p3;
            *(float2*)(Ps + (qm + gr) * PADP + nf * 8 + 2 * tc)     = make_float2(p0, p1);
            *(float2*)(Ps + (qm + gr + 8) * PADP + nf * 8 + 2 * tc) = make_float2(p2, p3);
        }
        ls0 += __shfl_xor_sync(0xffffffffu, ls0, 1);
        ls0 += __shfl_xor_sync(0xffffffffu, ls0, 2);
        ls1 += __shfl_xor_sync(0xffffffffu, ls1, 1);
        ls1 += __shfl_xor_sync(0xffffffffu, ls1, 2);
        l0 = l0 * corr0 + ls0;
        l1 = l1 * corr1 + ls1;
        #pragma unroll
        for (int nf = 0; nf < 4; nf++) {
            oa[nf][0] *= corr0; oa[nf][1] *= corr0;
            oa[nf][2] *= corr1; oa[nf][3] *= corr1;
        }
        __syncwarp();

        // ---- P @ V: plain tf32 ----
        #pragma unroll
        for (int ksj = 0; ksj < 16; ksj++) {
            const int j = ksj * 8;
            uint32_t afrag[4];
            afrag[0] = __float_as_uint(Ps[(qm + gr) * PADP + j + tc]);
            afrag[1] = __float_as_uint(Ps[(qm + gr + 8) * PADP + j + tc]);
            afrag[2] = __float_as_uint(Ps[(qm + gr) * PADP + j + tc + 4]);
            afrag[3] = __float_as_uint(Ps[(qm + gr + 8) * PADP + j + tc + 4]);
            #pragma unroll
            for (int nf = 0; nf < 4; nf++) {
                uint32_t bfrag[2];
                bfrag[0] = __float_as_uint(Vt[(nf * 8 + gr) * PADJ + j + tc]);
                bfrag[1] = __float_as_uint(Vt[(nf * 8 + gr) * PADJ + j + tc + 4]);
                MMA_TF32(oa[nf], afrag, bfrag);
            }
        }
    }

    // ---- write output ----
    const float inv0 = 1.0f / l0, inv1 = 1.0f / l1;
    const int r0 = q0 + qm + gr, r1 = r0 + 8;
    float* ob = o + (size_t)(b * NN) * 256 + h * 32;
    #pragma unroll
    for (int nf = 0; nf < 4; nf++) {
        const int d = nf * 8 + 2 * tc;
        *(float2*)(ob + (size_t)r0 * 256 + d) = make_float2(oa[nf][0] * inv0, oa[nf][1] * inv0);
        *(float2*)(ob + (size_t)r1 * 256 + d) = make_float2(oa[nf][2] * inv1, oa[nf][3] * inv1);
    }
}

// ================================ launch ====================================
extern "C" void kernel_launch(void* const* d_in, const int* in_sizes, int n_in,
                              void* d_out, int out_size)
{
    const float* x     = (const float*)d_in[0];
    const float* g1    = (const float*)d_in[2];
    const float* b1    = (const float*)d_in[3];
    const float* Wqkv  = (const float*)d_in[4];
    const float* Wproj = (const float*)d_in[5];
    const float* bproj = (const float*)d_in[6];
    const float* g2    = (const float*)d_in[7];
    const float* b2    = (const float*)d_in[8];
    const float* W1    = (const float*)d_in[9];
    const float* bb1   = (const float*)d_in[10];
    const float* W2    = (const float*)d_in[11];
    const float* bb2   = (const float*)d_in[12];
    float* out = (float*)d_out;

    float *p_h, *p_qkv, *p_o, *p_xn, *p_h2, *p_mid;
    cudaGetSymbolAddress((void**)&p_h,   g_h);
    cudaGetSymbolAddress((void**)&p_qkv, g_qkv);
    cudaGetSymbolAddress((void**)&p_o,   g_o);
    cudaGetSymbolAddress((void**)&p_xn,  g_xn);
    cudaGetSymbolAddress((void**)&p_h2,  g_h2);
    cudaGetSymbolAddress((void**)&p_mid, g_mid);

    cudaFuncSetAttribute(gemm_mma<false>, cudaFuncAttributeMaxDynamicSharedMemorySize, GEMM_DYN_BYTES);
    cudaFuncSetAttribute(gemm_mma<true>,  cudaFuncAttributeMaxDynamicSharedMemorySize, GEMM_DYN_BYTES);
    cudaFuncSetAttribute(attn_kernel,     cudaFuncAttributeMaxDynamicSharedMemorySize, ATTN_DYN_BYTES);

    // 1) h = LN1(x)
    ln_kernel<<<MROWS, 256>>>(x, g1, b1, p_h);

    // 2) qkv = h @ Wqkv^T   [grid (6,256)]
    gemm_mma<false><<<dim3(768 / 128, MROWS / 64), 256, GEMM_DYN_BYTES>>>(
        p_h, Wqkv, nullptr, nullptr, nullptr, p_qkv, MROWS, 3 * INF_, DD);

    // 3) attention -> o
    attn_kernel<<<dim3(NN / 128, BB * HH), 256, ATTN_DYN_BYTES>>>(p_qkv, p_o);

    // 4) xn = x + (o @ Wproj^T + bproj + h)   [grid (2,256)]
    gemm_mma<false><<<dim3(INF_ / 128, MROWS / 64), 256, GEMM_DYN_BYTES>>>(
        p_o, Wproj, bproj, p_h, x, p_xn, MROWS, INF_, INF_);

    // 5) h2 = LN2(xn)
    ln_kernel<<<MROWS, 256>>>(p_xn, g2, b2, p_h2);

    // 6) mid = gelu(h2 @ W1^T + bb1)   [grid (8,256)]
    gemm_mma<true><<<dim3(HID / 128, MROWS / 64), 256, GEMM_DYN_BYTES>>>(
        p_h2, W1, bb1, nullptr, nullptr, p_mid, MROWS, HID, DD);

    // 7) out = xn + mid @ W2^T + bb2   [grid (2,256)]
    gemm_mma<false><<<dim3(DD / 128, MROWS / 64), 256, GEMM_DYN_BYTES>>>(
        p_mid, W2, bb2, p_xn, nullptr, out, MROWS, DD, HID);
}

// round 15
// speedup vs baseline: 1.0857x; 1.0857x over previous
#include <cuda_runtime.h>
#include <cuda_bf16.h>
#include <math.h>
#include <cstdint>

// Problem constants
#define BB 16
#define NN 1024
#define DD 256
#define HH 8
#define INF_ 256
#define HID 1024
#define MROWS (BB * NN)   // 16384

// -------- scratch (device globals; no allocation allowed) --------
__device__ float g_h   [MROWS * DD];
__device__ float g_qkv [MROWS * 3 * INF_];
__device__ float g_o   [MROWS * INF_];
__device__ float g_xn  [MROWS * DD];
__device__ float g_h2  [MROWS * DD];
__device__ float g_mid [MROWS * HID];

// ===================== helpers =====================
__device__ __forceinline__ uint32_t smem_u32(const void* p) {
    uint32_t a;
    asm("{ .reg .u64 t; cvta.to.shared.u64 t, %1; cvt.u32.u64 %0, t; }"
        : "=r"(a) : "l"(p));
    return a;
}

#define CP_ASYNC16(dst, src) \
    asm volatile("cp.async.cg.shared.global [%0], [%1], 16;" :: "r"(dst), "l"(src))
#define CP_COMMIT() asm volatile("cp.async.commit_group;" ::: "memory")
#define CP_WAIT(n)  asm volatile("cp.async.wait_group %0;" :: "n"(n) : "memory")

// m16n8k8 tf32 mma (portable at plain sm_103 target)
#define MMA_TF32(c, a, b) \
    asm volatile("mma.sync.aligned.m16n8k8.row.col.f32.tf32.tf32.f32 " \
        "{%0,%1,%2,%3}, {%4,%5,%6,%7}, {%8,%9}, {%0,%1,%2,%3};" \
        : "+f"((c)[0]), "+f"((c)[1]), "+f"((c)[2]), "+f"((c)[3]) \
        : "r"((a)[0]), "r"((a)[1]), "r"((a)[2]), "r"((a)[3]), \
          "r"((b)[0]), "r"((b)[1]))

// ============ LayerNorm: warp-per-row, float4, shfl-only ====================
// block 256 = 8 warps = 8 rows; each lane owns 8 floats (2 x float4).
__global__ __launch_bounds__(256) void ln_kernel(
    const float* __restrict__ x, const float* __restrict__ g,
    const float* __restrict__ b, float* __restrict__ out)
{
    const int w = threadIdx.x >> 5, lane = threadIdx.x & 31;
    const int row = blockIdx.x * 8 + w;
    const float* xp = x + (size_t)row * DD + lane * 8;
    float4 v0 = *(const float4*)(xp);
    float4 v1 = *(const float4*)(xp + 4);
    float s1 = v0.x + v0.y + v0.z + v0.w + v1.x + v1.y + v1.z + v1.w;
    float s2 = v0.x*v0.x + v0.y*v0.y + v0.z*v0.z + v0.w*v0.w
             + v1.x*v1.x + v1.y*v1.y + v1.z*v1.z + v1.w*v1.w;
    #pragma unroll
    for (int o = 16; o; o >>= 1) {
        s1 += __shfl_xor_sync(0xffffffffu, s1, o);
        s2 += __shfl_xor_sync(0xffffffffu, s2, o);
    }
    const float mu  = s1 * (1.0f / DD);
    const float var = s2 * (1.0f / DD) - mu * mu;
    const float inv = rsqrtf(var + 1e-5f);
    const float4 gg0 = *(const float4*)(g + lane * 8);
    const float4 gg1 = *(const float4*)(g + lane * 8 + 4);
    const float4 bb0 = *(const float4*)(b + lane * 8);
    const float4 bb1 = *(const float4*)(b + lane * 8 + 4);
    float4 r0, r1;
    r0.x = (v0.x - mu) * inv * gg0.x + bb0.x;
    r0.y = (v0.y - mu) * inv * gg0.y + bb0.y;
    r0.z = (v0.z - mu) * inv * gg0.z + bb0.z;
    r0.w = (v0.w - mu) * inv * gg0.w + bb0.w;
    r1.x = (v1.x - mu) * inv * gg1.x + bb1.x;
    r1.y = (v1.y - mu) * inv * gg1.y + bb1.y;
    r1.z = (v1.z - mu) * inv * gg1.z + bb1.z;
    r1.w = (v1.w - mu) * inv * gg1.w + bb1.w;
    float* op = out + (size_t)row * DD + lane * 8;
    *(float4*)(op)     = r0;
    *(float4*)(op + 4) = r1;
}

// ============ tf32 mma.sync GEMM: C[M,N] = A[M,K]@B[N,K]^T + epilogue =======
// R13 config (proven best): 128x128 tile, 8 warps 2x4, warp tile 64x32, BK=32,
// 2-stage cp.async, ks-level fragment double buffering, 2 CTAs/SM.
#define PAD 36
#define GEMM_BUF_FLOATS (128 * PAD)
#define GEMM_DYN_BYTES (4 * GEMM_BUF_FLOATS * 4)

template <bool GELU>
__global__ __launch_bounds__(256, 2) void gemm_mma(
    const float* __restrict__ A, const float* __restrict__ Bm,
    const float* __restrict__ bias,
    const float* __restrict__ res1, const float* __restrict__ res2,
    float* __restrict__ C, int M, int Nn, int K)
{
    extern __shared__ float sm[];
    float* sAbuf = sm;
    float* sBbuf = sm + 2 * GEMM_BUF_FLOATS;

    const int tid = threadIdx.x;
    const int wid = tid >> 5, lane = tid & 31;
    const int bm = blockIdx.y * 128;
    const int bn = blockIdx.x * 128;
    const int wm = (wid >> 2) * 64;
    const int wn = (wid & 3) * 32;

    const int lr = tid >> 1;
    const int lc = (tid & 1) * 16;
    const float* Ag = A  + (size_t)(bm + lr) * K + lc;
    const float* Bg = Bm + (size_t)(bn + lr) * K + lc;
    const uint32_t sAa = smem_u32(sAbuf) + (lr * PAD + lc) * 4;
    const uint32_t sBa = smem_u32(sBbuf) + (lr * PAD + lc) * 4;
    const uint32_t bufBytes = GEMM_BUF_FLOATS * 4;

    float acc[4][4][4];
    #pragma unroll
    for (int mt = 0; mt < 4; mt++)
        #pragma unroll
        for (int nt = 0; nt < 4; nt++)
            #pragma unroll
            for (int q = 0; q < 4; q++) acc[mt][nt][q] = 0.f;

    const int NC = K >> 5;
    {
        #pragma unroll
        for (int i = 0; i < 4; i++) {
            CP_ASYNC16(sAa + i * 16, Ag + i * 4);
            CP_ASYNC16(sBa + i * 16, Bg + i * 4);
        }
        CP_COMMIT();
    }

    const int gr = lane >> 2;
    const int tc = lane & 3;

    for (int cc = 0; cc < NC; cc++) {
        if (cc + 1 < NC) {
            const int nb = (cc + 1) & 1;
            const float* ap = Ag + (cc + 1) * 32;
            const float* bp = Bg + (cc + 1) * 32;
            #pragma unroll
            for (int i = 0; i < 4; i++) {
                CP_ASYNC16(sAa + nb * bufBytes + i * 16, ap + i * 4);
                CP_ASYNC16(sBa + nb * bufBytes + i * 16, bp + i * 4);
            }
            CP_COMMIT();
            CP_WAIT(1);
        } else {
            CP_WAIT(0);
        }
        __syncthreads();

        const float* sA = sAbuf + (cc & 1) * GEMM_BUF_FLOATS;
        const float* sB = sBbuf + (cc & 1) * GEMM_BUF_FLOATS;

        uint32_t bfrag[2][4][2];
        uint32_t afrag[2][4][4];

        #pragma unroll
        for (int nt = 0; nt < 4; nt++) {
            const int n0 = wn + nt * 8 + gr;
            bfrag[0][nt][0] = __float_as_uint(sB[n0 * PAD + tc]);
            bfrag[0][nt][1] = __float_as_uint(sB[n0 * PAD + tc + 4]);
        }
        #pragma unroll
        for (int mt = 0; mt < 4; mt++) {
            const int r = wm + mt * 16 + gr;
            afrag[0][mt][0] = __float_as_uint(sA[r * PAD + tc]);
            afrag[0][mt][1] = __float_as_uint(sA[(r + 8) * PAD + tc]);
            afrag[0][mt][2] = __float_as_uint(sA[r * PAD + tc + 4]);
            afrag[0][mt][3] = __float_as_uint(sA[(r + 8) * PAD + tc + 4]);
        }

        #pragma unroll
        for (int ks = 0; ks < 4; ks++) {
            const int cur = ks & 1, nxt = cur ^ 1;
            if (ks < 3) {
                const int kb = (ks + 1) * 8;
                #pragma unroll
                for (int nt = 0; nt < 4; nt++) {
                    const int n0 = wn + nt * 8 + gr;
                    bfrag[nxt][nt][0] = __float_as_uint(sB[n0 * PAD + kb + tc]);
                    bfrag[nxt][nt][1] = __float_as_uint(sB[n0 * PAD + kb + tc + 4]);
                }
                #pragma unroll
                for (int mt = 0; mt < 4; mt++) {
                    const int r = wm + mt * 16 + gr;
                    afrag[nxt][mt][0] = __float_as_uint(sA[r * PAD + kb + tc]);
                    afrag[nxt][mt][1] = __float_as_uint(sA[(r + 8) * PAD + kb + tc]);
                    afrag[nxt][mt][2] = __float_as_uint(sA[r * PAD + kb + tc + 4]);
                    afrag[nxt][mt][3] = __float_as_uint(sA[(r + 8) * PAD + kb + tc + 4]);
                }
            }
            #pragma unroll
            for (int mt = 0; mt < 4; mt++)
                #pragma unroll
                for (int nt = 0; nt < 4; nt++)
                    MMA_TF32(acc[mt][nt], afrag[cur][mt], bfrag[cur][nt]);
        }
        __syncthreads();
    }

    #pragma unroll
    for (int mt = 0; mt < 4; mt++) {
        #pragma unroll
        for (int nt = 0; nt < 4; nt++) {
            const int col = bn + wn + nt * 8 + 2 * tc;
            #pragma unroll
            for (int half = 0; half < 2; half++) {
                const int row = bm + wm + mt * 16 + gr + half * 8;
                float v0 = acc[mt][nt][half * 2 + 0];
                float v1 = acc[mt][nt][half * 2 + 1];
                if (bias) { v0 += bias[col]; v1 += bias[col + 1]; }
                if (GELU) {
                    v0 = 0.5f * v0 * (1.0f + erff(v0 * 0.70710678118654752f));
                    v1 = 0.5f * v1 * (1.0f + erff(v1 * 0.70710678118654752f));
                }
                const size_t idx = (size_t)row * Nn + col;
                if (res1) { v0 += res1[idx]; v1 += res1[idx + 1]; }
                if (res2) { v0 += res2[idx]; v1 += res2[idx + 1]; }
                *(float2*)(C + idx) = make_float2(v0, v1);
            }
        }
    }
}

// ====== Attention: tensor-core flash, plain tf32 QK and PV ==================
// CTA: 128 q-rows of one (b,h); 8 warps, warp w owns q rows [w*16, w*16+16).
// 8 K-tiles of 128 keys. Q,K pad-36; Vt[32][132]; P pad-132.
#define PADJ 132
#define PADP 132
#define AQ_OFF 0                        // Qs [128][36]
#define AK_OFF (128 * PAD)              // Ks [128][36]
#define AV_OFF (AK_OFF + 128 * PAD)     // Vt [32][132]
#define AP_OFF (AV_OFF + 32 * PADJ)     // Ps [128][132]
#define ATTN_SMEM_FLOATS (AP_OFF + 128 * PADP)
#define ATTN_DYN_BYTES   (ATTN_SMEM_FLOATS * 4)

__global__ __launch_bounds__(256) void attn_kernel(
    const float* __restrict__ qkv, float* __restrict__ o)
{
    extern __shared__ float sm[];
    float* Qs = sm + AQ_OFF;
    float* Ks = sm + AK_OFF;
    float* Vt = sm + AV_OFF;
    float* Ps = sm + AP_OFF;

    const int tid = threadIdx.x;
    const int b = blockIdx.y >> 3, h = blockIdx.y & 7;
    const int q0 = blockIdx.x * 128;
    const int w = tid >> 5, lane = tid & 31;
    const int gr = lane >> 2, tc = lane & 3;
    const int qm = w * 16;
    const int par = tid & 1;
    const float scale = 0.17677669529663687f; // 1/sqrt(32)

    // ---- load Q tile (scaled) ----
    {
        const int rr = tid >> 1, cb = par * 16;
        const float* qp = qkv + ((size_t)(b * NN + q0 + rr) * 768) + h * 32 + cb;
        #pragma unroll
        for (int i = 0; i < 16; i += 4) {
            float4 v = *(const float4*)(qp + i);
            Qs[rr * PAD + cb + i + 0] = v.x * scale;
            Qs[rr * PAD + cb + i + 1] = v.y * scale;
            Qs[rr * PAD + cb + i + 2] = v.z * scale;
            Qs[rr * PAD + cb + i + 3] = v.w * scale;
        }
    }

    float oa[4][4];
    #pragma unroll
    for (int nf = 0; nf < 4; nf++)
        #pragma unroll
        for (int q = 0; q < 4; q++) oa[nf][q] = 0.f;
    float m0 = -1e30f, m1 = -1e30f, l0 = 0.f, l1 = 0.f;

    for (int kt = 0; kt < NN / 128; kt++) {   // 8 tiles — exactly N=1024 keys
        const int k0 = kt * 128;
        __syncthreads();   // protect Ks/Vt from previous tile's readers
        // ---- load K (rows) and V (transposed) ----
        {
            const int rr = tid >> 1, cb = par * 16;
            const float* kp = qkv + ((size_t)(b * NN + k0 + rr) * 768) + 256 + h * 32 + cb;
            const float* vp = kp + 256;
            float vv[16];
            #pragma unroll
            for (int i = 0; i < 16; i += 4) {
                float4 kv = *(const float4*)(kp + i);
                Ks[rr * PAD + cb + i + 0] = kv.x;
                Ks[rr * PAD + cb + i + 1] = kv.y;
                Ks[rr * PAD + cb + i + 2] = kv.z;
                Ks[rr * PAD + cb + i + 3] = kv.w;
                float4 vq = *(const float4*)(vp + i);
                vv[i + 0] = vq.x; vv[i + 1] = vq.y; vv[i + 2] = vq.z; vv[i + 3] = vq.w;
            }
            #pragma unroll
            for (int ii = 0; ii < 16; ii++) {     // parity stagger kills 2-way conflict
                int i = (ii + par) & 15;
                Vt[(cb + i) * PADJ + rr] = vv[i];
            }
        }
        __syncthreads();

        // ---- QK^T: plain tf32 ----
        float sc[16][4];
        #pragma unroll
        for (int nf = 0; nf < 16; nf++)
            #pragma unroll
            for (int q = 0; q < 4; q++) sc[nf][q] = 0.f;
        #pragma unroll
        for (int ks = 0; ks < 4; ks++) {
            const int kb = ks * 8;
            uint32_t afrag[4];
            afrag[0] = __float_as_uint(Qs[(qm + gr) * PAD + kb + tc]);
            afrag[1] = __float_as_uint(Qs[(qm + gr + 8) * PAD + kb + tc]);
            afrag[2] = __float_as_uint(Qs[(qm + gr) * PAD + kb + tc + 4]);
            afrag[3] = __float_as_uint(Qs[(qm + gr + 8) * PAD + kb + tc + 4]);
            #pragma unroll
            for (int nf = 0; nf < 16; nf++) {
                uint32_t bfrag[2];
                bfrag[0] = __float_as_uint(Ks[(nf * 8 + gr) * PAD + kb + tc]);
                bfrag[1] = __float_as_uint(Ks[(nf * 8 + gr) * PAD + kb + tc + 4]);
                MMA_TF32(sc[nf], afrag, bfrag);
            }
        }

        // ---- online softmax on accumulator layout ----
        float tm0 = -1e30f, tm1 = -1e30f;
        #pragma unroll
        for (int nf = 0; nf < 16; nf++) {
            tm0 = fmaxf(tm0, fmaxf(sc[nf][0], sc[nf][1]));
            tm1 = fmaxf(tm1, fmaxf(sc[nf][2], sc[nf][3]));
        }
        tm0 = fmaxf(tm0, __shfl_xor_sync(0xffffffffu, tm0, 1));
        tm0 = fmaxf(tm0, __shfl_xor_sync(0xffffffffu, tm0, 2));
        tm1 = fmaxf(tm1, __shfl_xor_sync(0xffffffffu, tm1, 1));
        tm1 = fmaxf(tm1, __shfl_xor_sync(0xffffffffu, tm1, 2));
        float mn0 = fmaxf(m0, tm0), mn1 = fmaxf(m1, tm1);
        float corr0 = __expf(m0 - mn0), corr1 = __expf(m1 - mn1);
        m0 = mn0; m1 = mn1;
        float ls0 = 0.f, ls1 = 0.f;
        #pragma unroll
        for (int nf = 0; nf < 16; nf++) {
            float p0 = __expf(sc[nf][0] - mn0);
            float p1 = __expf(sc[nf][1] - mn0);
            float p2 = __expf(sc[nf][2] - mn1);
            float p3 = __expf(sc[nf][3] - mn1);
            ls0 += p0 + p1; ls1 += p2 + p3;
            *(float2*)(Ps + (qm + gr) * PADP + nf * 8 + 2 * tc)     = make_float2(p0, p1);
            *(float2*)(Ps + (qm + gr + 8) * PADP + nf * 8 + 2 * tc) = make_float2(p2, p3);
        }
        ls0 += __shfl_xor_sync(0xffffffffu, ls0, 1);
        ls0 += __shfl_xor_sync(0xffffffffu, ls0, 2);
        ls1 += __shfl_xor_sync(0xffffffffu, ls1, 1);
        ls1 += __shfl_xor_sync(0xffffffffu, ls1, 2);
        l0 = l0 * corr0 + ls0;
        l1 = l1 * corr1 + ls1;
        #pragma unroll
        for (int nf = 0; nf < 4; nf++) {
            oa[nf][0] *= corr0; oa[nf][1] *= corr0;
            oa[nf][2] *= corr1; oa[nf][3] *= corr1;
        }
        __syncwarp();

        // ---- P @ V: plain tf32 ----
        #pragma unroll
        for (int ksj = 0; ksj < 16; ksj++) {
            const int j = ksj * 8;
            uint32_t afrag[4];
            afrag[0] = __float_as_uint(Ps[(qm + gr) * PADP + j + tc]);
            afrag[1] = __float_as_uint(Ps[(qm + gr + 8) * PADP + j + tc]);
            afrag[2] = __float_as_uint(Ps[(qm + gr) * PADP + j + tc + 4]);
            afrag[3] = __float_as_uint(Ps[(qm + gr + 8) * PADP + j + tc + 4]);
            #pragma unroll
            for (int nf = 0; nf < 4; nf++) {
                uint32_t bfrag[2];
                bfrag[0] = __float_as_uint(Vt[(nf * 8 + gr) * PADJ + j + tc]);
                bfrag[1] = __float_as_uint(Vt[(nf * 8 + gr) * PADJ + j + tc + 4]);
                MMA_TF32(oa[nf], afrag, bfrag);
            }
        }
    }

    // ---- write output ----
    const float inv0 = 1.0f / l0, inv1 = 1.0f / l1;
    const int r0 = q0 + qm + gr, r1 = r0 + 8;
    float* ob = o + (size_t)(b * NN) * 256 + h * 32;
    #pragma unroll
    for (int nf = 0; nf < 4; nf++) {
        const int d = nf * 8 + 2 * tc;
        *(float2*)(ob + (size_t)r0 * 256 + d) = make_float2(oa[nf][0] * inv0, oa[nf][1] * inv0);
        *(float2*)(ob + (size_t)r1 * 256 + d) = make_float2(oa[nf][2] * inv1, oa[nf][3] * inv1);
    }
}

// ================================ launch ====================================
extern "C" void kernel_launch(void* const* d_in, const int* in_sizes, int n_in,
                              void* d_out, int out_size)
{
    const float* x     = (const float*)d_in[0];
    const float* g1    = (const float*)d_in[2];
    const float* b1    = (const float*)d_in[3];
    const float* Wqkv  = (const float*)d_in[4];
    const float* Wproj = (const float*)d_in[5];
    const float* bproj = (const float*)d_in[6];
    const float* g2    = (const float*)d_in[7];
    const float* b2    = (const float*)d_in[8];
    const float* W1    = (const float*)d_in[9];
    const float* bb1   = (const float*)d_in[10];
    const float* W2    = (const float*)d_in[11];
    const float* bb2   = (const float*)d_in[12];
    float* out = (float*)d_out;

    float *p_h, *p_qkv, *p_o, *p_xn, *p_h2, *p_mid;
    cudaGetSymbolAddress((void**)&p_h,   g_h);
    cudaGetSymbolAddress((void**)&p_qkv, g_qkv);
    cudaGetSymbolAddress((void**)&p_o,   g_o);
    cudaGetSymbolAddress((void**)&p_xn,  g_xn);
    cudaGetSymbolAddress((void**)&p_h2,  g_h2);
    cudaGetSymbolAddress((void**)&p_mid, g_mid);

    cudaFuncSetAttribute(gemm_mma<false>, cudaFuncAttributeMaxDynamicSharedMemorySize, GEMM_DYN_BYTES);
    cudaFuncSetAttribute(gemm_mma<true>,  cudaFuncAttributeMaxDynamicSharedMemorySize, GEMM_DYN_BYTES);
    cudaFuncSetAttribute(attn_kernel,     cudaFuncAttributeMaxDynamicSharedMemorySize, ATTN_DYN_BYTES);

    // 1) h = LN1(x)
    ln_kernel<<<MROWS / 8, 256>>>(x, g1, b1, p_h);

    // 2) qkv = h @ Wqkv^T
    gemm_mma<false><<<dim3(768 / 128, MROWS / 128), 256, GEMM_DYN_BYTES>>>(
        p_h, Wqkv, nullptr, nullptr, nullptr, p_qkv, MROWS, 3 * INF_, DD);

    // 3) attention -> o
    attn_kernel<<<dim3(NN / 128, BB * HH), 256, ATTN_DYN_BYTES>>>(p_qkv, p_o);

    // 4) xn = x + (o @ Wproj^T + bproj + h)
    gemm_mma<false><<<dim3(INF_ / 128, MROWS / 128), 256, GEMM_DYN_BYTES>>>(
        p_o, Wproj, bproj, p_h, x, p_xn, MROWS, INF_, INF_);

    // 5) h2 = LN2(xn)
    ln_kernel<<<MROWS / 8, 256>>>(p_xn, g2, b2, p_h2);

    // 6) mid = gelu(h2 @ W1^T + bb1)
    gemm_mma<true><<<dim3(HID / 128, MROWS / 128), 256, GEMM_DYN_BYTES>>>(
        p_h2, W1, bb1, nullptr, nullptr, p_mid, MROWS, HID, DD);

    // 7) out = xn + mid @ W2^T + bb2
    gemm_mma<false><<<dim3(DD / 128, MROWS / 128), 256, GEMM_DYN_BYTES>>>(
        p_mid, W2, bb2, p_xn, nullptr, out, MROWS, DD, HID);
}